// round 3
// baseline (speedup 1.0000x reference)
#include <cuda_runtime.h>

#define NN 200000
#define EE 6400000
#define FF 128
#define HH 16
#define CC 40

// ---------------- scratch (static device globals; 16B-aligned types) --------
__device__ int    g_is64;               // 1 if edge_index is int64, 0 if int32
__device__ int    g_count[NN];          // edges with dst == i (excl. self loop)
__device__ float  g_dis[NN];            // rsqrt(deg incl. self loop)
__device__ int    g_rowptr[NN];         // CSR row start (exclusive scan of count)
__device__ int    g_cursor[NN];         // fill cursors
__device__ int    g_partial[256];       // scan partials
__device__ float2 g_csr[EE];            // {src as int bits, weight}
__device__ float4 g_t[NN * 10];         // post-GEMM features (4 or 10 float4/node)
__device__ float4 g_aggA[NN * 10];      // agg ping
__device__ float4 g_aggB[NN * 10];      // agg pong / final 40-wide agg

// ---------------- edge dtype probe ------------------------------------------
// int64 little-endian values in [0, 2e5): every odd 32-bit word is 0.
// int32 data: odd words are random edge indices, ~surely nonzero somewhere.
__global__ void k_probe(const unsigned int* __restrict__ w) {
    __shared__ int s_any;
    if (threadIdx.x == 0) s_any = 0;
    __syncthreads();
    if (w[2 * threadIdx.x + 1] != 0u) s_any = 1;   // benign race, all write 1
    __syncthreads();
    if (threadIdx.x == 0) g_is64 = s_any ? 0 : 1;
}

__device__ __forceinline__ int load_src(const void* ei, int e) {
    int s = g_is64 ? (int)((const long long*)ei)[e] : ((const int*)ei)[e];
    return min(max(s, 0), NN - 1);
}
__device__ __forceinline__ int load_dst(const void* ei, int e) {
    int d = g_is64 ? (int)((const long long*)ei)[EE + e] : ((const int*)ei)[EE + e];
    return min(max(d, 0), NN - 1);
}

// ---------------- precompute ------------------------------------------------
__global__ void k_zero_count() {
    int i = blockIdx.x * blockDim.x + threadIdx.x;
    if (i < NN) g_count[i] = 0;
}

__global__ void k_deg(const void* __restrict__ ei) {
    int e = blockIdx.x * blockDim.x + threadIdx.x;
    if (e < EE) atomicAdd(&g_count[load_dst(ei, e)], 1);
}

__global__ void k_dis() {
    int i = blockIdx.x * blockDim.x + threadIdx.x;
    if (i < NN) g_dis[i] = rsqrtf((float)(g_count[i] + 1));
}

// block-level exclusive scan of g_count -> g_rowptr (local), totals -> g_partial
__global__ void k_scan_block() {
    __shared__ int warpsum[32];
    int idx  = blockIdx.x * 1024 + threadIdx.x;
    int lane = threadIdx.x & 31;
    int wid  = threadIdx.x >> 5;
    int v = (idx < NN) ? g_count[idx] : 0;
    int x = v;
    #pragma unroll
    for (int o = 1; o < 32; o <<= 1) {
        int y = __shfl_up_sync(0xffffffffu, x, o);
        if (lane >= o) x += y;
    }
    if (lane == 31) warpsum[wid] = x;
    __syncthreads();
    if (wid == 0) {
        int s = warpsum[lane];
        #pragma unroll
        for (int o = 1; o < 32; o <<= 1) {
            int y = __shfl_up_sync(0xffffffffu, s, o);
            if (lane >= o) s += y;
        }
        warpsum[lane] = s;
    }
    __syncthreads();
    int base = (wid > 0) ? warpsum[wid - 1] : 0;
    int incl = base + x;
    if (idx < NN) g_rowptr[idx] = incl - v;   // exclusive
    if (threadIdx.x == 1023) g_partial[blockIdx.x] = incl;
}

__global__ void k_scan_partials(int nb) {
    int s = 0;
    for (int i = 0; i < nb; i++) { int v = g_partial[i]; g_partial[i] = s; s += v; }
}

__global__ void k_scan_add() {
    int idx = blockIdx.x * 1024 + threadIdx.x;
    if (idx < NN) {
        int r = g_rowptr[idx] + g_partial[blockIdx.x];
        g_rowptr[idx] = r;
        g_cursor[idx] = r;
    }
}

__global__ void k_csr_fill(const void* __restrict__ ei) {
    int e = blockIdx.x * blockDim.x + threadIdx.x;
    if (e < EE) {
        int s = load_src(ei, e);
        int d = load_dst(ei, e);
        int pos = atomicAdd(&g_cursor[d], 1);
        pos = min(max(pos, 0), EE - 1);
        g_csr[pos] = make_float2(__int_as_float(s), g_dis[s] * g_dis[d]);
    }
}

// ---------------- dense layers (GEMM + self-loop init fused) ----------------
__global__ void k_gemm_in(const float* __restrict__ x, const float* __restrict__ w) {
    __shared__ float sW[FF * HH];
    for (int i = threadIdx.x; i < FF * HH; i += blockDim.x) sW[i] = w[i];
    __syncthreads();
    int n = blockIdx.x * blockDim.x + threadIdx.x;
    if (n >= NN) return;
    float acc[HH];
    #pragma unroll
    for (int c = 0; c < HH; c++) acc[c] = 0.f;
    const float4* xr = (const float4*)(x + (size_t)n * FF);
    #pragma unroll 4
    for (int k4 = 0; k4 < FF / 4; k4++) {
        float4 xv = xr[k4];
        const float* wk = sW + k4 * 4 * HH;
        #pragma unroll
        for (int c = 0; c < HH; c++)
            acc[c] += xv.x * wk[c] + xv.y * wk[HH + c] + xv.z * wk[2 * HH + c] + xv.w * wk[3 * HH + c];
    }
    float dv = g_dis[n];
    float d2 = dv * dv;
    #pragma unroll
    for (int q = 0; q < 4; q++) {
        float4 tv = make_float4(acc[q * 4], acc[q * 4 + 1], acc[q * 4 + 2], acc[q * 4 + 3]);
        g_t[n * 4 + q] = tv;
        g_aggA[n * 4 + q] = make_float4(tv.x * d2, tv.y * d2, tv.z * d2, tv.w * d2);
    }
}

// hidden layer GEMM: reads relu(aggIn + bias), writes t and aggOut = t*dis^2
__global__ void k_gemm_hid(const float* __restrict__ w, const float* __restrict__ bias, int inSel) {
    __shared__ float sW[HH * HH];
    __shared__ float sB[HH];
    if (threadIdx.x < HH * HH) sW[threadIdx.x] = w[threadIdx.x];
    if (threadIdx.x < HH) sB[threadIdx.x] = bias[threadIdx.x];
    __syncthreads();
    int n = blockIdx.x * blockDim.x + threadIdx.x;
    if (n >= NN) return;
    const float4* aggIn = inSel ? g_aggB : g_aggA;
    float4* aggOut = inSel ? g_aggA : g_aggB;
    float in[HH];
    #pragma unroll
    for (int q = 0; q < 4; q++) {
        float4 v = aggIn[n * 4 + q];
        in[q * 4] = v.x; in[q * 4 + 1] = v.y; in[q * 4 + 2] = v.z; in[q * 4 + 3] = v.w;
    }
    #pragma unroll
    for (int k = 0; k < HH; k++) in[k] = fmaxf(in[k] + sB[k], 0.f);
    float acc[HH];
    #pragma unroll
    for (int c = 0; c < HH; c++) acc[c] = 0.f;
    #pragma unroll
    for (int k = 0; k < HH; k++) {
        float xv = in[k];
        #pragma unroll
        for (int c = 0; c < HH; c++) acc[c] += xv * sW[k * HH + c];
    }
    float dv = g_dis[n];
    float d2 = dv * dv;
    #pragma unroll
    for (int q = 0; q < 4; q++) {
        float4 tv = make_float4(acc[q * 4], acc[q * 4 + 1], acc[q * 4 + 2], acc[q * 4 + 3]);
        g_t[n * 4 + q] = tv;
        aggOut[n * 4 + q] = make_float4(tv.x * d2, tv.y * d2, tv.z * d2, tv.w * d2);
    }
}

// output GEMM: reads relu(aggA + bias7), width 16 -> 40, writes t and aggB init
__global__ void k_gemm_out(const float* __restrict__ w, const float* __restrict__ bias) {
    __shared__ float sW[HH * CC];
    __shared__ float sB[HH];
    for (int i = threadIdx.x; i < HH * CC; i += blockDim.x) sW[i] = w[i];
    if (threadIdx.x < HH) sB[threadIdx.x] = bias[threadIdx.x];
    __syncthreads();
    int n = blockIdx.x * blockDim.x + threadIdx.x;
    if (n >= NN) return;
    float in[HH];
    #pragma unroll
    for (int q = 0; q < 4; q++) {
        float4 v = g_aggA[n * 4 + q];
        in[q * 4] = v.x; in[q * 4 + 1] = v.y; in[q * 4 + 2] = v.z; in[q * 4 + 3] = v.w;
    }
    #pragma unroll
    for (int k = 0; k < HH; k++) in[k] = fmaxf(in[k] + sB[k], 0.f);
    float acc[CC];
    #pragma unroll
    for (int c = 0; c < CC; c++) acc[c] = 0.f;
    #pragma unroll
    for (int k = 0; k < HH; k++) {
        float xv = in[k];
        #pragma unroll
        for (int c = 0; c < CC; c++) acc[c] += xv * sW[k * CC + c];
    }
    float dv = g_dis[n];
    float d2 = dv * dv;
    #pragma unroll
    for (int q = 0; q < CC / 4; q++) {
        float4 tv = make_float4(acc[q * 4], acc[q * 4 + 1], acc[q * 4 + 2], acc[q * 4 + 3]);
        g_t[n * 10 + q] = tv;
        g_aggB[n * 10 + q] = make_float4(tv.x * d2, tv.y * d2, tv.z * d2, tv.w * d2);
    }
}

// ---------------- sparse aggregation (CSR, atomic-free) ---------------------
// 4 lanes/node, one float4 each = 16 features. agg preloaded with self-loop term.
__global__ void k_spmm16(int sel) {
    int gid = blockIdx.x * blockDim.x + threadIdx.x;
    int node = gid >> 2;
    if (node >= NN) return;
    int lane = gid & 3;
    float4* agg = sel ? g_aggB : g_aggA;
    const float4* __restrict__ T = g_t;
    int beg = g_rowptr[node];
    int cnt = g_count[node];
    float4 acc = agg[node * 4 + lane];
    const float2* ep = g_csr + beg;
    int i = 0;
    for (; i + 4 <= cnt; i += 4) {
        float2 e0 = ep[i], e1 = ep[i + 1], e2 = ep[i + 2], e3 = ep[i + 3];
        float4 v0 = T[__float_as_int(e0.x) * 4 + lane];
        float4 v1 = T[__float_as_int(e1.x) * 4 + lane];
        float4 v2 = T[__float_as_int(e2.x) * 4 + lane];
        float4 v3 = T[__float_as_int(e3.x) * 4 + lane];
        acc.x += e0.y * v0.x + e1.y * v1.x + e2.y * v2.x + e3.y * v3.x;
        acc.y += e0.y * v0.y + e1.y * v1.y + e2.y * v2.y + e3.y * v3.y;
        acc.z += e0.y * v0.z + e1.y * v1.z + e2.y * v2.z + e3.y * v3.z;
        acc.w += e0.y * v0.w + e1.y * v1.w + e2.y * v2.w + e3.y * v3.w;
    }
    for (; i < cnt; i++) {
        float2 e = ep[i];
        float4 v = T[__float_as_int(e.x) * 4 + lane];
        acc.x += e.y * v.x; acc.y += e.y * v.y; acc.z += e.y * v.z; acc.w += e.y * v.w;
    }
    agg[node * 4 + lane] = acc;
}

// 10 lanes/node, one float4 each = 40 features. agg = g_aggB (preinit by gemm_out).
__global__ void k_spmm40() {
    int gid = blockIdx.x * blockDim.x + threadIdx.x;
    int node = gid / 10;
    if (node >= NN) return;
    int lane = gid - node * 10;
    const float4* __restrict__ T = g_t;
    int beg = g_rowptr[node];
    int cnt = g_count[node];
    float4 acc = g_aggB[node * 10 + lane];
    const float2* ep = g_csr + beg;
    int i = 0;
    for (; i + 2 <= cnt; i += 2) {
        float2 e0 = ep[i], e1 = ep[i + 1];
        float4 v0 = T[__float_as_int(e0.x) * 10 + lane];
        float4 v1 = T[__float_as_int(e1.x) * 10 + lane];
        acc.x += e0.y * v0.x + e1.y * v1.x;
        acc.y += e0.y * v0.y + e1.y * v1.y;
        acc.z += e0.y * v0.z + e1.y * v1.z;
        acc.w += e0.y * v0.w + e1.y * v1.w;
    }
    for (; i < cnt; i++) {
        float2 e = ep[i];
        float4 v = T[__float_as_int(e.x) * 10 + lane];
        acc.x += e.y * v.x; acc.y += e.y * v.y; acc.z += e.y * v.z; acc.w += e.y * v.w;
    }
    g_aggB[node * 10 + lane] = acc;
}

// ---------------- log_softmax (warp per node, C = 40) -----------------------
__global__ void k_softmax(const float* __restrict__ b_out, float* __restrict__ out) {
    int t = blockIdx.x * blockDim.x + threadIdx.x;
    int node = t >> 5;
    if (node >= NN) return;
    int lane = t & 31;
    const float* row = ((const float*)g_aggB) + (size_t)node * CC;
    float v0 = row[lane] + b_out[lane];
    float v1 = (lane < 8) ? (row[32 + lane] + b_out[32 + lane]) : -1e30f;
    float m = fmaxf(v0, v1);
    #pragma unroll
    for (int o = 16; o > 0; o >>= 1) m = fmaxf(m, __shfl_xor_sync(0xffffffffu, m, o));
    float s = expf(v0 - m) + ((lane < 8) ? expf(v1 - m) : 0.f);
    #pragma unroll
    for (int o = 16; o > 0; o >>= 1) s += __shfl_xor_sync(0xffffffffu, s, o);
    float l = logf(s);
    out[(size_t)node * CC + lane] = v0 - m - l;
    if (lane < 8) out[(size_t)node * CC + 32 + lane] = v1 - m - l;
}

// ---------------- launch ----------------------------------------------------
extern "C" void kernel_launch(void* const* d_in, const int* in_sizes, int n_in,
                              void* d_out, int out_size) {
    const float* x      = (const float*)d_in[0];
    const float* w_in   = (const float*)d_in[1];
    const float* b_in   = (const float*)d_in[2];
    const float* w_hid  = (const float*)d_in[3];
    const float* b_hid  = (const float*)d_in[4];
    const float* w_out  = (const float*)d_in[5];
    const float* b_out  = (const float*)d_in[6];
    const void*  ei     = (const void*)d_in[7];
    float* out = (float*)d_out;

    const int TB = 256;
    const int nbN = (NN + TB - 1) / TB;
    const int nbE = (EE + TB - 1) / TB;
    const int nbScan = (NN + 1023) / 1024;   // 196

    // edge dtype probe + precompute: degrees, normalization, CSR by dst
    k_probe<<<1, 1024>>>((const unsigned int*)ei);
    k_zero_count<<<nbN, TB>>>();
    k_deg<<<nbE, TB>>>(ei);
    k_dis<<<nbN, TB>>>();
    k_scan_block<<<nbScan, 1024>>>();
    k_scan_partials<<<1, 1>>>(nbScan);
    k_scan_add<<<nbScan, 1024>>>();
    k_csr_fill<<<nbE, TB>>>(ei);

    // layer 0: x @ w_in -> t ; aggA preinit; aggregate
    k_gemm_in<<<nbN, TB>>>(x, w_in);
    k_spmm16<<<(NN * 4 + TB - 1) / TB, TB>>>(0);

    // 8 hidden layers (bias of the PREVIOUS conv is applied on read)
    for (int i = 0; i < 8; i++) {
        int inSel = i & 1;  // 0: read A write B, 1: read B write A
        const float* bias = (i == 0) ? b_in : (b_hid + (i - 1) * HH);
        k_gemm_hid<<<nbN, TB>>>(w_hid + i * HH * HH, bias, inSel);
        k_spmm16<<<(NN * 4 + TB - 1) / TB, TB>>>(1 - inSel);
    }

    // output layer: relu(aggA + b_hid[7]) @ w_out -> t40 ; aggB preinit; aggregate
    k_gemm_out<<<nbN, TB>>>(w_out, b_hid + 7 * HH);
    k_spmm40<<<(NN * 10 + TB - 1) / TB, TB>>>();

    // log_softmax(aggB + b_out) -> out
    k_softmax<<<(NN * 32 + TB - 1) / TB, TB>>>(b_out, out);
}

// round 6
// speedup vs baseline: 1.2266x; 1.2266x over previous
#include <cuda_runtime.h>

#define NN 200000
#define EE 6400000
#define FF 128
#define HH 16
#define CC 40

// ---------------- scratch (static device globals; 16B-aligned types) --------
__device__ int    g_is64;               // 1 if edge_index is int64, 0 if int32
__device__ int    g_count[NN];          // edges with dst == i (excl. self loop)
__device__ float  g_dis[NN];            // rsqrt(deg incl. self loop)
__device__ int    g_rowptr[NN];         // CSR row start (exclusive scan of count)
__device__ int    g_cursor[NN];         // fill cursors
__device__ int    g_partial[256];       // scan partials
__device__ float2 g_csr[EE];            // {src as int bits, weight}
__device__ float4 g_H[2][NN * 4];       // feature ping-pong (16 floats/node)
__device__ float4 g_S[2][NN * 4];       // self-loop init ping-pong (dis^2 * h)

// ---------------- edge dtype probe ------------------------------------------
__global__ void k_probe(const unsigned int* __restrict__ w) {
    __shared__ int s_any;
    if (threadIdx.x == 0) s_any = 0;
    __syncthreads();
    if (w[2 * threadIdx.x + 1] != 0u) s_any = 1;
    __syncthreads();
    if (threadIdx.x == 0) g_is64 = s_any ? 0 : 1;
}

__device__ __forceinline__ int load_src(const void* ei, int e) {
    int s = g_is64 ? (int)((const long long*)ei)[e] : ((const int*)ei)[e];
    return min(max(s, 0), NN - 1);
}
__device__ __forceinline__ int load_dst(const void* ei, int e) {
    int d = g_is64 ? (int)((const long long*)ei)[EE + e] : ((const int*)ei)[EE + e];
    return min(max(d, 0), NN - 1);
}

// ---------------- precompute ------------------------------------------------
__global__ void k_zero_count() {
    int i = blockIdx.x * blockDim.x + threadIdx.x;
    if (i < NN) g_count[i] = 0;
}

__global__ void k_deg(const void* __restrict__ ei) {
    int e = blockIdx.x * blockDim.x + threadIdx.x;
    if (e < EE) atomicAdd(&g_count[load_dst(ei, e)], 1);
}

__global__ void k_dis() {
    int i = blockIdx.x * blockDim.x + threadIdx.x;
    if (i < NN) g_dis[i] = rsqrtf((float)(g_count[i] + 1));
}

__global__ void k_scan_block() {
    __shared__ int warpsum[32];
    int idx  = blockIdx.x * 1024 + threadIdx.x;
    int lane = threadIdx.x & 31;
    int wid  = threadIdx.x >> 5;
    int v = (idx < NN) ? g_count[idx] : 0;
    int x = v;
    #pragma unroll
    for (int o = 1; o < 32; o <<= 1) {
        int y = __shfl_up_sync(0xffffffffu, x, o);
        if (lane >= o) x += y;
    }
    if (lane == 31) warpsum[wid] = x;
    __syncthreads();
    if (wid == 0) {
        int s = warpsum[lane];
        #pragma unroll
        for (int o = 1; o < 32; o <<= 1) {
            int y = __shfl_up_sync(0xffffffffu, s, o);
            if (lane >= o) s += y;
        }
        warpsum[lane] = s;
    }
    __syncthreads();
    int base = (wid > 0) ? warpsum[wid - 1] : 0;
    int incl = base + x;
    if (idx < NN) g_rowptr[idx] = incl - v;
    if (threadIdx.x == 1023) g_partial[blockIdx.x] = incl;
}

__global__ void k_scan_partials(int nb) {
    int s = 0;
    for (int i = 0; i < nb; i++) { int v = g_partial[i]; g_partial[i] = s; s += v; }
}

__global__ void k_scan_add() {
    int idx = blockIdx.x * 1024 + threadIdx.x;
    if (idx < NN) {
        int r = g_rowptr[idx] + g_partial[blockIdx.x];
        g_rowptr[idx] = r;
        g_cursor[idx] = r;
    }
}

__global__ void k_csr_fill(const void* __restrict__ ei) {
    int e = blockIdx.x * blockDim.x + threadIdx.x;
    if (e < EE) {
        int s = load_src(ei, e);
        int d = load_dst(ei, e);
        int pos = atomicAdd(&g_cursor[d], 1);
        pos = min(max(pos, 0), EE - 1);
        g_csr[pos] = make_float2(__int_as_float(s), g_dis[s] * g_dis[d]);
    }
}

// ---------------- input GEMM: t0 = x @ w_in; write H[0], S[0] ---------------
__global__ void k_gemm_in(const float* __restrict__ x, const float* __restrict__ w) {
    __shared__ float sW[FF * HH];
    for (int i = threadIdx.x; i < FF * HH; i += blockDim.x) sW[i] = w[i];
    __syncthreads();
    int n = blockIdx.x * blockDim.x + threadIdx.x;
    if (n >= NN) return;
    float acc[HH];
    #pragma unroll
    for (int c = 0; c < HH; c++) acc[c] = 0.f;
    const float4* xr = (const float4*)(x + (size_t)n * FF);
    #pragma unroll 4
    for (int k4 = 0; k4 < FF / 4; k4++) {
        float4 xv = xr[k4];
        const float* wk = sW + k4 * 4 * HH;
        #pragma unroll
        for (int c = 0; c < HH; c++)
            acc[c] += xv.x * wk[c] + xv.y * wk[HH + c] + xv.z * wk[2 * HH + c] + xv.w * wk[3 * HH + c];
    }
    float dv = g_dis[n];
    float d2 = dv * dv;
    #pragma unroll
    for (int q = 0; q < 4; q++) {
        float4 tv = make_float4(acc[q * 4], acc[q * 4 + 1], acc[q * 4 + 2], acc[q * 4 + 3]);
        g_H[0][n * 4 + q] = tv;
        g_S[0][n * 4 + q] = make_float4(tv.x * d2, tv.y * d2, tv.z * d2, tv.w * d2);
    }
}

// ---------------- fused layer: aggregate 16-wide, then epilogue -------------
__global__ void k_spmm_fused(const float* __restrict__ w, const float* __restrict__ bias,
                             int cur, int useGemm) {
    __shared__ float sW[HH * HH];
    __shared__ float sB[HH];
    if (useGemm && threadIdx.x < HH * HH) sW[threadIdx.x] = w[threadIdx.x];
    if (threadIdx.x < HH) sB[threadIdx.x] = bias[threadIdx.x];
    __syncthreads();

    int gid = blockIdx.x * blockDim.x + threadIdx.x;
    int node = gid >> 2;
    if (node >= NN) return;
    int lane = gid & 3;
    int wl = threadIdx.x & 31;
    int gbase = wl & ~3;

    const float4* __restrict__ T = g_H[cur];
    int beg = g_rowptr[node];
    int cnt = g_count[node];
    float4 acc = g_S[cur][node * 4 + lane];
    const float2* ep = g_csr + beg;
    int i = 0;
    for (; i + 8 <= cnt; i += 8) {
        float2 e0 = ep[i],     e1 = ep[i + 1], e2 = ep[i + 2], e3 = ep[i + 3];
        float2 e4 = ep[i + 4], e5 = ep[i + 5], e6 = ep[i + 6], e7 = ep[i + 7];
        float4 v0 = T[__float_as_int(e0.x) * 4 + lane];
        float4 v1 = T[__float_as_int(e1.x) * 4 + lane];
        float4 v2 = T[__float_as_int(e2.x) * 4 + lane];
        float4 v3 = T[__float_as_int(e3.x) * 4 + lane];
        float4 v4 = T[__float_as_int(e4.x) * 4 + lane];
        float4 v5 = T[__float_as_int(e5.x) * 4 + lane];
        float4 v6 = T[__float_as_int(e6.x) * 4 + lane];
        float4 v7 = T[__float_as_int(e7.x) * 4 + lane];
        acc.x += e0.y * v0.x + e1.y * v1.x + e2.y * v2.x + e3.y * v3.x
               + e4.y * v4.x + e5.y * v5.x + e6.y * v6.x + e7.y * v7.x;
        acc.y += e0.y * v0.y + e1.y * v1.y + e2.y * v2.y + e3.y * v3.y
               + e4.y * v4.y + e5.y * v5.y + e6.y * v6.y + e7.y * v7.y;
        acc.z += e0.y * v0.z + e1.y * v1.z + e2.y * v2.z + e3.y * v3.z
               + e4.y * v4.z + e5.y * v5.z + e6.y * v6.z + e7.y * v7.z;
        acc.w += e0.y * v0.w + e1.y * v1.w + e2.y * v2.w + e3.y * v3.w
               + e4.y * v4.w + e5.y * v5.w + e6.y * v6.w + e7.y * v7.w;
    }
    for (; i < cnt; i++) {
        float2 e = ep[i];
        float4 v = T[__float_as_int(e.x) * 4 + lane];
        acc.x += e.y * v.x; acc.y += e.y * v.y; acc.z += e.y * v.z; acc.w += e.y * v.w;
    }

    float4 h;
    if (useGemm) {
        float a[HH];
        #pragma unroll
        for (int j = 0; j < 4; j++) {
            a[j * 4 + 0] = __shfl_sync(0xffffffffu, acc.x, gbase + j);
            a[j * 4 + 1] = __shfl_sync(0xffffffffu, acc.y, gbase + j);
            a[j * 4 + 2] = __shfl_sync(0xffffffffu, acc.z, gbase + j);
            a[j * 4 + 3] = __shfl_sync(0xffffffffu, acc.w, gbase + j);
        }
        float o[4];
        #pragma unroll
        for (int c = 0; c < 4; c++) o[c] = sB[lane * 4 + c];
        #pragma unroll
        for (int k = 0; k < HH; k++) {
            float av = a[k];
            const float* wr = sW + k * HH + lane * 4;
            o[0] += av * wr[0]; o[1] += av * wr[1]; o[2] += av * wr[2]; o[3] += av * wr[3];
        }
        h = make_float4(fmaxf(o[0], 0.f), fmaxf(o[1], 0.f), fmaxf(o[2], 0.f), fmaxf(o[3], 0.f));
    } else {
        h = make_float4(fmaxf(acc.x + sB[lane * 4], 0.f),
                        fmaxf(acc.y + sB[lane * 4 + 1], 0.f),
                        fmaxf(acc.z + sB[lane * 4 + 2], 0.f),
                        fmaxf(acc.w + sB[lane * 4 + 3], 0.f));
    }
    float dv = g_dis[node];
    float d2 = dv * dv;
    int nxt = cur ^ 1;
    g_H[nxt][node * 4 + lane] = h;
    g_S[nxt][node * 4 + lane] = make_float4(h.x * d2, h.y * d2, h.z * d2, h.w * d2);
}

// ---------------- final fused: aggregate + 16->40 GEMM + log_softmax --------
__global__ void k_spmm_out(const float* __restrict__ w, const float* __restrict__ bias,
                           int cur, float* __restrict__ out) {
    __shared__ float sW[HH * CC];
    __shared__ float sB[CC];
    for (int i = threadIdx.x; i < HH * CC; i += blockDim.x) sW[i] = w[i];
    if (threadIdx.x < CC) sB[threadIdx.x] = bias[threadIdx.x];
    __syncthreads();

    int gid = blockIdx.x * blockDim.x + threadIdx.x;
    int node = gid >> 2;
    if (node >= NN) return;
    int lane = gid & 3;
    int wl = threadIdx.x & 31;
    int gbase = wl & ~3;

    const float4* __restrict__ T = g_H[cur];
    int beg = g_rowptr[node];
    int cnt = g_count[node];
    float4 acc = g_S[cur][node * 4 + lane];
    const float2* ep = g_csr + beg;
    int i = 0;
    for (; i + 8 <= cnt; i += 8) {
        float2 e0 = ep[i],     e1 = ep[i + 1], e2 = ep[i + 2], e3 = ep[i + 3];
        float2 e4 = ep[i + 4], e5 = ep[i + 5], e6 = ep[i + 6], e7 = ep[i + 7];
        float4 v0 = T[__float_as_int(e0.x) * 4 + lane];
        float4 v1 = T[__float_as_int(e1.x) * 4 + lane];
        float4 v2 = T[__float_as_int(e2.x) * 4 + lane];
        float4 v3 = T[__float_as_int(e3.x) * 4 + lane];
        float4 v4 = T[__float_as_int(e4.x) * 4 + lane];
        float4 v5 = T[__float_as_int(e5.x) * 4 + lane];
        float4 v6 = T[__float_as_int(e6.x) * 4 + lane];
        float4 v7 = T[__float_as_int(e7.x) * 4 + lane];
        acc.x += e0.y * v0.x + e1.y * v1.x + e2.y * v2.x + e3.y * v3.x
               + e4.y * v4.x + e5.y * v5.x + e6.y * v6.x + e7.y * v7.x;
        acc.y += e0.y * v0.y + e1.y * v1.y + e2.y * v2.y + e3.y * v3.y
               + e4.y * v4.y + e5.y * v5.y + e6.y * v6.y + e7.y * v7.y;
        acc.z += e0.y * v0.z + e1.y * v1.z + e2.y * v2.z + e3.y * v3.z
               + e4.y * v4.z + e5.y * v5.z + e6.y * v6.z + e7.y * v7.z;
        acc.w += e0.y * v0.w + e1.y * v1.w + e2.y * v2.w + e3.y * v3.w
               + e4.y * v4.w + e5.y * v5.w + e6.y * v6.w + e7.y * v7.w;
    }
    for (; i < cnt; i++) {
        float2 e = ep[i];
        float4 v = T[__float_as_int(e.x) * 4 + lane];
        acc.x += e.y * v.x; acc.y += e.y * v.y; acc.z += e.y * v.z; acc.w += e.y * v.w;
    }

    float a[HH];
    #pragma unroll
    for (int j = 0; j < 4; j++) {
        a[j * 4 + 0] = __shfl_sync(0xffffffffu, acc.x, gbase + j);
        a[j * 4 + 1] = __shfl_sync(0xffffffffu, acc.y, gbase + j);
        a[j * 4 + 2] = __shfl_sync(0xffffffffu, acc.z, gbase + j);
        a[j * 4 + 3] = __shfl_sync(0xffffffffu, acc.w, gbase + j);
    }
    float o[10];
    #pragma unroll
    for (int c = 0; c < 10; c++) o[c] = sB[lane * 10 + c];
    #pragma unroll
    for (int k = 0; k < HH; k++) {
        float av = a[k];
        const float* wr = sW + k * CC + lane * 10;
        #pragma unroll
        for (int c = 0; c < 10; c++) o[c] += av * wr[c];
    }
    float m = o[0];
    #pragma unroll
    for (int c = 1; c < 10; c++) m = fmaxf(m, o[c]);
    m = fmaxf(m, __shfl_xor_sync(0xffffffffu, m, 1));
    m = fmaxf(m, __shfl_xor_sync(0xffffffffu, m, 2));
    float s = 0.f;
    #pragma unroll
    for (int c = 0; c < 10; c++) s += expf(o[c] - m);
    s += __shfl_xor_sync(0xffffffffu, s, 1);
    s += __shfl_xor_sync(0xffffffffu, s, 2);
    float l = m + logf(s);
    float2* op = (float2*)(out + (size_t)node * CC + lane * 10);
    #pragma unroll
    for (int c = 0; c < 5; c++) op[c] = make_float2(o[2 * c] - l, o[2 * c + 1] - l);
}

// ---------------- launch ----------------------------------------------------
extern "C" void kernel_launch(void* const* d_in, const int* in_sizes, int n_in,
                              void* d_out, int out_size) {
    const float* x      = (const float*)d_in[0];
    const float* w_in   = (const float*)d_in[1];
    const float* b_in   = (const float*)d_in[2];
    const float* w_hid  = (const float*)d_in[3];
    const float* b_hid  = (const float*)d_in[4];
    const float* w_out  = (const float*)d_in[5];
    const float* b_out  = (const float*)d_in[6];
    const void*  ei     = (const void*)d_in[7];
    float* out = (float*)d_out;

    const int TB = 256;
    const int nbN = (NN + TB - 1) / TB;
    const int nbE = (EE + TB - 1) / TB;
    const int nbScan = (NN + 1023) / 1024;
    const int nbG = (NN * 4) / TB;   // 3125, exact

    k_probe<<<1, 1024>>>((const unsigned int*)ei);
    k_zero_count<<<nbN, TB>>>();
    k_deg<<<nbE, TB>>>(ei);
    k_dis<<<nbN, TB>>>();
    k_scan_block<<<nbScan, 1024>>>();
    k_scan_partials<<<1, 1>>>(nbScan);
    k_scan_add<<<nbScan, 1024>>>();
    k_csr_fill<<<nbE, TB>>>(ei);

    k_gemm_in<<<nbN, TB>>>(x, w_in);
    k_spmm_fused<<<nbG, TB>>>(nullptr, b_in, 0, 0);
    for (int k = 1; k <= 8; k++) {
        k_spmm_fused<<<nbG, TB>>>(w_hid + (k - 1) * HH * HH, b_hid + (k - 1) * HH, k & 1, 1);
    }
    k_spmm_out<<<nbG, TB>>>(w_out, b_out, 1, out);
}